// round 11
// baseline (speedup 1.0000x reference)
#include <cuda_runtime.h>
#include <cuda_fp16.h>

#define HH 512
#define WW 512
#define NCH 32            // B*C = 8*4
#define HW (HH * WW)
#define KIT 10
#define NBLK 1024         // persistent grid; 7/SM x 148 SMs = 1036 >= 1024 resident

// Scratch (static device globals — no allocation)
__device__ __half   g_hbuf[2][NCH * HW];   // ping-pong raw erosion fields (2 x 16MB)
__device__ unsigned g_minbits[KIT][NCH];
__device__ unsigned g_maxbits[KIT][NCH];
__device__ double   g_sum[KIT][NCH];
__device__ unsigned g_bar[KIT];

__global__ void init_stats_kernel() {
    int i = threadIdx.x;
    if (i < KIT * NCH) {
        ((unsigned*)g_minbits)[i] = 0x7f800000u;  // +inf
        ((unsigned*)g_maxbits)[i] = 0u;           // erosion >= 0
        ((double*)g_sum)[i] = 0.0;
    }
    if (i < KIT) g_bar[i] = 0u;
}

// Grid-wide barrier: release fence -> arrive -> spin -> acquire fence.
// __threadfence() (gpu scope) also invalidates L1D; field reads use __ldcg anyway.
__device__ __forceinline__ void grid_barrier(int it, int tid) {
    __syncthreads();
    if (tid == 0) {
        __threadfence();
        unsigned prev = atomicAdd(&g_bar[it], 1u);
        if (prev != NBLK - 1u) {
            while (*(volatile unsigned*)&g_bar[it] < NBLK) __nanosleep(50);
        }
        __threadfence();
    }
    __syncthreads();
}

// Persistent kernel: all KIT erosion iterations + final loss, one launch.
//
// Deferred-normalization identity (zero padding of the NORMALIZED field):
//   0.2*sum norm(x_i) - 0.5 = (0.2*inv)*S_raw - (n_present*0.2*inv*mn + 0.5)
// Fields stored as fp16 raw erosion; stats computed from the ROUNDED values so
// normalization constants match what the next iteration convolves.
__global__ void __launch_bounds__(256, 7)
persist_kernel(const float* __restrict__ pred,
               const int* __restrict__ tgt,
               float* __restrict__ outp) {
    __shared__ float rmin[8], rmax[8], rsum[8];

    const int tid    = threadIdx.x;
    const int lane   = tid & 31;
    const int warp   = tid >> 5;
    const int t      = blockIdx.x;           // fixed tile: 32 ch x 32 ybands
    const int ch     = t >> 5;
    const int yband  = t & 31;
    const int warp_x = warp & 3;             // 4 warps across x (128 cols each)
    const int warp_y = warp >> 2;            // 2 warps across y (8 rows each)
    const int x0     = warp_x * 128 + lane * 4;
    const int y0     = yband * 16 + warp_y * 8;

    const bool left_edge  = (x0 == 0);
    const bool right_edge = (x0 + 3 == WW - 1);
    const bool need_l = (lane == 0)  && !left_edge;
    const bool need_r = (lane == 31) && !right_edge;

    const float* __restrict__ pch = pred + (size_t)ch * HW;
    const int* __restrict__ tch   = tgt + (size_t)(ch >> 2) * HW;
    const int cls = ch & 3;

    for (int it = 0; it < KIT; ++it) {
        float mn = 0.0f, inv = 1.0f;
        if (it > 0) {
            float a = __uint_as_float(__ldcg(&g_minbits[it - 1][ch]));
            float b = __uint_as_float(__ldcg(&g_maxbits[it - 1][ch]));
            float d = b - a;
            if (d != 0.0f) { mn = a; inv = 1.0f / d; }
        }
        const float A     = 0.2f * inv;
        const float DELTA = 0.2f * inv * mn;
        const float BINT  = -(5.0f * DELTA + 0.5f);
        const float mx0 = left_edge  ? DELTA : 0.0f;
        const float mx3 = right_edge ? DELTA : 0.0f;

        const __half* __restrict__ in = g_hbuf[(it & 1) ^ 1] + (size_t)ch * HW;
        __half* __restrict__ out      = g_hbuf[it & 1] + (size_t)ch * HW;
        const bool first = (it == 0);
        const bool wr    = (it != KIT - 1);

        auto load4 = [&](int y) -> float4 {
            if ((unsigned)y >= HH) return make_float4(0.f, 0.f, 0.f, 0.f);
            if (first) {
                float4 p = *(const float4*)(pch + y * WW + x0);
                int4   tg = *(const int4*)(tch + y * WW + x0);
                float4 v;
                v.x = p.x - (tg.x == cls ? 1.0f : 0.0f); v.x *= v.x;
                v.y = p.y - (tg.y == cls ? 1.0f : 0.0f); v.y *= v.y;
                v.z = p.z - (tg.z == cls ? 1.0f : 0.0f); v.z *= v.z;
                v.w = p.w - (tg.w == cls ? 1.0f : 0.0f); v.w *= v.w;
                return v;
            }
            uint2 v = __ldcg((const uint2*)(in + y * WW + x0));
            __half2 h01 = *(const __half2*)&v.x;
            __half2 h23 = *(const __half2*)&v.y;
            float2 fa = __half22float2(h01), fb = __half22float2(h23);
            return make_float4(fa.x, fa.y, fb.x, fb.y);
        };
        auto load1 = [&](int y, int x) -> float {   // x in-bounds at call sites
            if (first) {
                float p = pch[y * WW + x];
                float v = p - (tch[y * WW + x] == cls ? 1.0f : 0.0f);
                return v * v;
            }
            return __half2float(__ushort_as_half(
                __ldcg((const unsigned short*)(in + y * WW + x))));
        };

        float4 u = load4(y0 - 1);
        float4 c = load4(y0);

        float lmin = __uint_as_float(0x7f800000u);
        float lmax = 0.0f;
        float lsum = 0.0f;

#pragma unroll
        for (int i = 0; i < 8; ++i) {
            const int y = y0 + i;
            const float4 d = load4(y + 1);

            float l = __shfl_up_sync(0xffffffffu, c.w, 1);
            float r = __shfl_down_sync(0xffffffffu, c.x, 1);
            if (need_l) l = load1(y, x0 - 1);
            if (need_r) r = load1(y, x0 + 4);
            if (left_edge)  l = 0.0f;
            if (right_edge) r = 0.0f;

            const float S0 = (c.x + u.x) + (d.x + l)   + c.y;
            const float S1 = (c.y + u.y) + (d.y + c.x) + c.z;
            const float S2 = (c.z + u.z) + (d.z + c.y) + c.w;
            const float S3 = (c.w + u.w) + (d.w + c.z) + r;

            const float b  = (y == 0 || y == HH - 1) ? (BINT + DELTA) : BINT;
            const float e0 = fmaxf(fmaf(A, S0, b + mx0), 0.0f);
            const float e1 = fmaxf(fmaf(A, S1, b), 0.0f);
            const float e2 = fmaxf(fmaf(A, S2, b), 0.0f);
            const float e3 = fmaxf(fmaf(A, S3, b + mx3), 0.0f);

            // Round to fp16; use ROUNDED values for both store and stats.
            __half2 p0 = __floats2half2_rn(e0, e1);
            __half2 p1 = __floats2half2_rn(e2, e3);
            if (wr) {
                uint2 s;
                *(__half2*)&s.x = p0;
                *(__half2*)&s.y = p1;
                *(uint2*)(out + y * WW + x0) = s;
            }
            float2 q0 = __half22float2(p0), q1 = __half22float2(p1);

            lmin = fminf(lmin, fminf(fminf(q0.x, q0.y), fminf(q1.x, q1.y)));
            lmax = fmaxf(lmax, fmaxf(fmaxf(q0.x, q0.y), fmaxf(q1.x, q1.y)));
            lsum += (q0.x + q0.y) + (q1.x + q1.y);

            u = c; c = d;
        }

        // warp -> block -> global stats
#pragma unroll
        for (int o = 16; o; o >>= 1) {
            lmin = fminf(lmin, __shfl_xor_sync(0xffffffffu, lmin, o));
            lmax = fmaxf(lmax, __shfl_xor_sync(0xffffffffu, lmax, o));
            lsum += __shfl_xor_sync(0xffffffffu, lsum, o);
        }
        if (lane == 0) { rmin[warp] = lmin; rmax[warp] = lmax; rsum[warp] = lsum; }
        __syncthreads();
        if (tid == 0) {
            float bm = rmax[0], bn = rmin[0], bs = rsum[0];
#pragma unroll
            for (int i = 1; i < 8; ++i) {
                bm = fmaxf(bm, rmax[i]);
                bn = fminf(bn, rmin[i]);
                bs += rsum[i];
            }
            atomicMax(&g_maxbits[it][ch], __float_as_uint(bm));
            atomicMin(&g_minbits[it][ch], __float_as_uint(bn));
            atomicAdd(&g_sum[it][ch], (double)bs);
        }

        grid_barrier(it, tid);
    }

    // Final loss (all iter-9 stats visible after last barrier)
    if (t == 0 && tid == 0) {
        double total = 0.0;
        for (int k = 0; k < KIT; ++k) {
            double w = (double)(k + 1) * (double)(k + 1);  // (k+1)^2
            for (int c = 0; c < NCH; ++c) {
                float mnf = __uint_as_float(__ldcg(&g_minbits[k][c]));
                float mxf = __uint_as_float(__ldcg(&g_maxbits[k][c]));
                double S  = __ldcg(&g_sum[k][c]);
                float d   = mxf - mnf;
                double ns = (d != 0.0f)
                          ? (S - (double)HW * (double)mnf) / (double)d
                          : S;
                total += w * ns;
            }
        }
        outp[0] = (float)(total / (double)((double)NCH * (double)HW));
    }
}

extern "C" void kernel_launch(void* const* d_in, const int* in_sizes, int n_in,
                              void* d_out, int out_size) {
    const float* pred = (const float*)d_in[0];
    const int* tgt    = (const int*)d_in[1];

    init_stats_kernel<<<1, 512>>>();
    persist_kernel<<<NBLK, 256>>>(pred, tgt, (float*)d_out);
}

// round 12
// speedup vs baseline: 2.3727x; 2.3727x over previous
#include <cuda_runtime.h>
#include <cuda_fp16.h>

#define HH 512
#define WW 512
#define NCH 32            // B*C = 8*4
#define HW (HH * WW)
#define KIT 10

// Scratch (static device globals — no allocation)
__device__ __half   g_hbuf[2][NCH * HW];   // ping-pong raw erosion fields (2 x 16MB)
__device__ unsigned g_minbits[KIT][NCH];
__device__ unsigned g_maxbits[KIT][NCH];
__device__ double   g_sum[KIT][NCH];

__global__ void init_stats_kernel() {
    int i = threadIdx.x;
    if (i < KIT * NCH) {
        ((unsigned*)g_minbits)[i] = 0x7f800000u;  // +inf
        ((unsigned*)g_maxbits)[i] = 0u;           // erosion >= 0
        ((double*)g_sum)[i] = 0.0;
    }
}

// One erosion iteration. Each thread: 4 cols x 8 rows, rolling 3-row window.
// Horizontal halo via warp shuffle. Fields stored as fp16 raw erosion; stats
// computed from the ROUNDED values so the normalization constants match what
// the next iteration convolves.
//
// Deferred-normalization identity (zero padding of the NORMALIZED field):
//   0.2*sum norm(x_i) - 0.5 = (0.2*inv)*S_raw - (n_present*0.2*inv*mn + 0.5)
template <bool FIRST, bool WRITE>
__global__ void __launch_bounds__(256, 8)
erode_step_kernel(const float* __restrict__ pred,
                  const int* __restrict__ tgt,
                  int iter, int src) {
    __shared__ float rmin[8], rmax[8], rsum[8];

    const int ch     = blockIdx.z;
    const int tid    = threadIdx.x;
    const int lane   = tid & 31;
    const int warp   = tid >> 5;
    const int warp_x = warp & 3;             // 4 warps across x (128 cols each)
    const int warp_y = warp >> 2;            // 2 warps across y (8 rows each)
    const int x0     = warp_x * 128 + lane * 4;
    const int y0     = blockIdx.y * 16 + warp_y * 8;

    float mn = 0.0f, inv = 1.0f;
    if (!FIRST) {
        float a = __uint_as_float(g_minbits[iter - 1][ch]);
        float b = __uint_as_float(g_maxbits[iter - 1][ch]);
        float d = b - a;
        if (d != 0.0f) { mn = a; inv = 1.0f / d; }
    }
    const float A     = 0.2f * inv;
    const float DELTA = 0.2f * inv * mn;           // per-present-tap correction
    const float BINT  = -(5.0f * DELTA + 0.5f);    // all-5-taps bias

    const __half* __restrict__ in = g_hbuf[src] + (size_t)ch * HW;
    __half* __restrict__ out      = g_hbuf[FIRST ? 0 : (src ^ 1)] + (size_t)ch * HW;
    const float* __restrict__ pch = pred + (size_t)ch * HW;
    const int* __restrict__ tch   = tgt + (size_t)(ch >> 2) * HW;
    const int cls = ch & 3;

    auto load4 = [&](int y) -> float4 {
        if ((unsigned)y >= HH) return make_float4(0.f, 0.f, 0.f, 0.f);
        if (FIRST) {
            float4 p = *(const float4*)(pch + y * WW + x0);
            int4   t = *(const int4*)(tch + y * WW + x0);
            float4 v;
            v.x = p.x - (t.x == cls ? 1.0f : 0.0f); v.x *= v.x;
            v.y = p.y - (t.y == cls ? 1.0f : 0.0f); v.y *= v.y;
            v.z = p.z - (t.z == cls ? 1.0f : 0.0f); v.z *= v.z;
            v.w = p.w - (t.w == cls ? 1.0f : 0.0f); v.w *= v.w;
            return v;
        }
        uint2 v = *(const uint2*)(in + y * WW + x0);
        float2 fa = __half22float2(*(const __half2*)&v.x);
        float2 fb = __half22float2(*(const __half2*)&v.y);
        return make_float4(fa.x, fa.y, fb.x, fb.y);
    };
    auto load1 = [&](int y, int x) -> float {      // x in-bounds at call sites
        if (FIRST) {
            float p = pch[y * WW + x];
            float v = p - (tch[y * WW + x] == cls ? 1.0f : 0.0f);
            return v * v;
        }
        return __half2float(in[y * WW + x]);
    };

    const bool left_edge  = (x0 == 0);             // elem 0 has no left tap
    const bool right_edge = (x0 + 3 == WW - 1);    // elem 3 has no right tap
    const float mx0 = left_edge  ? DELTA : 0.0f;
    const float mx3 = right_edge ? DELTA : 0.0f;
    const bool need_l = (lane == 0)  && !left_edge;
    const bool need_r = (lane == 31) && !right_edge;

    float4 u = load4(y0 - 1);
    float4 c = load4(y0);

    float lmin = __uint_as_float(0x7f800000u);
    float lmax = 0.0f;
    float lsum = 0.0f;

#pragma unroll
    for (int i = 0; i < 8; ++i) {
        const int y = y0 + i;
        const float4 d = load4(y + 1);

        float l = __shfl_up_sync(0xffffffffu, c.w, 1);
        float r = __shfl_down_sync(0xffffffffu, c.x, 1);
        if (need_l) l = load1(y, x0 - 1);
        if (need_r) r = load1(y, x0 + 4);
        if (left_edge)  l = 0.0f;
        if (right_edge) r = 0.0f;

        const float S0 = (c.x + u.x) + (d.x + l)   + c.y;
        const float S1 = (c.y + u.y) + (d.y + c.x) + c.z;
        const float S2 = (c.z + u.z) + (d.z + c.y) + c.w;
        const float S3 = (c.w + u.w) + (d.w + c.z) + r;

        const float b  = (y == 0 || y == HH - 1) ? (BINT + DELTA) : BINT;
        const float e0 = fmaxf(fmaf(A, S0, b + mx0), 0.0f);
        const float e1 = fmaxf(fmaf(A, S1, b), 0.0f);
        const float e2 = fmaxf(fmaf(A, S2, b), 0.0f);
        const float e3 = fmaxf(fmaf(A, S3, b + mx3), 0.0f);

        // Round to fp16; use ROUNDED values for both store and stats.
        __half2 p0 = __floats2half2_rn(e0, e1);
        __half2 p1 = __floats2half2_rn(e2, e3);
        if (WRITE) {
            uint2 s;
            *(__half2*)&s.x = p0;
            *(__half2*)&s.y = p1;
            *(uint2*)(out + y * WW + x0) = s;
        }
        float2 q0 = __half22float2(p0), q1 = __half22float2(p1);

        lmin = fminf(lmin, fminf(fminf(q0.x, q0.y), fminf(q1.x, q1.y)));
        lmax = fmaxf(lmax, fmaxf(fmaxf(q0.x, q0.y), fmaxf(q1.x, q1.y)));
        lsum += (q0.x + q0.y) + (q1.x + q1.y);

        u = c; c = d;
    }

    // ---- reduction: warp -> block -> global atomics ----
#pragma unroll
    for (int o = 16; o; o >>= 1) {
        lmin = fminf(lmin, __shfl_xor_sync(0xffffffffu, lmin, o));
        lmax = fmaxf(lmax, __shfl_xor_sync(0xffffffffu, lmax, o));
        lsum += __shfl_xor_sync(0xffffffffu, lsum, o);
    }
    if (lane == 0) {
        rmin[warp] = lmin; rmax[warp] = lmax; rsum[warp] = lsum;
    }
    __syncthreads();
    if (tid == 0) {
        float bm = rmax[0], bn = rmin[0];
        float bs = rsum[0];
#pragma unroll
        for (int i = 1; i < 8; ++i) {
            bm = fmaxf(bm, rmax[i]);
            bn = fminf(bn, rmin[i]);
            bs += rsum[i];
        }
        atomicMax(&g_maxbits[iter][ch], __float_as_uint(bm));
        atomicMin(&g_minbits[iter][ch], __float_as_uint(bn));
        atomicAdd(&g_sum[iter][ch], (double)bs);
    }
}

__global__ void finalize_kernel(float* __restrict__ outp) {
    if (threadIdx.x == 0) {
        double total = 0.0;
        for (int k = 0; k < KIT; ++k) {
            double w = (double)(k + 1) * (double)(k + 1);  // (k+1)^2
            for (int c = 0; c < NCH; ++c) {
                float mnf = __uint_as_float(g_minbits[k][c]);
                float mxf = __uint_as_float(g_maxbits[k][c]);
                double S  = g_sum[k][c];
                float d   = mxf - mnf;
                double ns = (d != 0.0f)
                          ? (S - (double)HW * (double)mnf) / (double)d
                          : S;
                total += w * ns;
            }
        }
        outp[0] = (float)(total / (double)((double)NCH * (double)HW));
    }
}

extern "C" void kernel_launch(void* const* d_in, const int* in_sizes, int n_in,
                              void* d_out, int out_size) {
    const float* pred = (const float*)d_in[0];
    const int* tgt    = (const int*)d_in[1];

    init_stats_kernel<<<1, 512>>>();

    dim3 block(256);
    dim3 grid(1, HH / 16, NCH);  // (1, 32, 32): block covers 512 cols x 16 rows

    // iter 0: bound = (pred - onehot)^2 computed on the fly, writes g_hbuf[0]
    erode_step_kernel<true, true><<<grid, block>>>(pred, tgt, 0, 0);

    // iters 1..8: ping-pong, normalization pushed through the conv
    int src = 0;
    for (int k = 1; k < KIT - 1; ++k) {
        erode_step_kernel<false, true><<<grid, block>>>(pred, tgt, k, src);
        src ^= 1;
    }
    // iter 9: stats only, no field store
    erode_step_kernel<false, false><<<grid, block>>>(pred, tgt, KIT - 1, src);

    finalize_kernel<<<1, 32>>>((float*)d_out);
}

// round 13
// speedup vs baseline: 2.6470x; 1.1156x over previous
#include <cuda_runtime.h>
#include <cuda_fp16.h>

#define HH 512
#define WW 512
#define NCH 32            // B*C = 8*4
#define HW (HH * WW)
#define KIT 10

// Scratch (static device globals — no allocation)
__device__ __half   g_hbuf[2][NCH * HW];   // ping-pong raw erosion fields (2 x 16MB)
__device__ unsigned g_minbits[KIT][NCH];
__device__ unsigned g_maxbits[KIT][NCH];
__device__ double   g_sum[KIT][NCH];

__global__ void init_stats_kernel() {
    int i = threadIdx.x;
    if (i < KIT * NCH) {
        ((unsigned*)g_minbits)[i] = 0x7f800000u;  // +inf
        ((unsigned*)g_maxbits)[i] = 0u;           // erosion >= 0
        ((double*)g_sum)[i] = 0.0;
    }
}

// One erosion iteration. Thread: 4 cols x 8 rows, rolling 3-row half2 window.
// Steady-state math in native half2 SIMD. Legitimacy: normalization
// (e-min)/(max-min) is affine-invariant, so fp16 constant precision cancels;
// only per-element rounding noise (same order as fp16 storage) survives.
//
// Deferred-normalization identity (zero padding of the NORMALIZED field):
//   0.2*sum norm(x_i) - 0.5 = (0.2*inv)*S_raw - (n_present*0.2*inv*mn + 0.5)
template <bool FIRST, bool WRITE>
__global__ void __launch_bounds__(256, 8)
erode_step_kernel(const float* __restrict__ pred,
                  const int* __restrict__ tgt,
                  int iter, int src) {
    __shared__ float rmin[8], rmax[8], rsum[8];

    const int ch     = blockIdx.z;
    const int tid    = threadIdx.x;
    const int lane   = tid & 31;
    const int warp   = tid >> 5;
    const int warp_x = warp & 3;             // 4 warps across x (128 cols each)
    const int warp_y = warp >> 2;            // 2 warps across y (8 rows each)
    const int x0     = warp_x * 128 + lane * 4;
    const int y0     = blockIdx.y * 16 + warp_y * 8;

    float mn = 0.0f, inv = 1.0f;
    if (!FIRST) {
        float a = __uint_as_float(g_minbits[iter - 1][ch]);
        float b = __uint_as_float(g_maxbits[iter - 1][ch]);
        float d = b - a;
        if (d != 0.0f) { mn = a; inv = 1.0f / d; }
    }
    const float A     = 0.2f * inv;
    const float DELTA = 0.2f * inv * mn;           // per-present-tap correction
    const float BINT  = -(5.0f * DELTA + 0.5f);    // all-5-taps bias

    const __half* __restrict__ in = g_hbuf[src] + (size_t)ch * HW;
    __half* __restrict__ out      = g_hbuf[FIRST ? 0 : (src ^ 1)] + (size_t)ch * HW;
    const float* __restrict__ pch = pred + (size_t)ch * HW;
    const int* __restrict__ tch   = tgt + (size_t)(ch >> 2) * HW;
    const int cls = ch & 3;

    const bool left_edge  = (x0 == 0);
    const bool right_edge = (x0 + 3 == WW - 1);
    const float mx0f = left_edge  ? DELTA : 0.0f;
    const float mx3f = right_edge ? DELTA : 0.0f;
    const bool need_l = (lane == 0)  && !left_edge;
    const bool need_r = (lane == 31) && !right_edge;

    float lmin = __uint_as_float(0x7f800000u);
    float lmax = 0.0f;
    float lsum = 0.0f;

    if (FIRST) {
        // fp32 path: bound=(pred-onehot)^2 on the fly. mn=0 -> bias = -0.5.
        auto load4 = [&](int y) -> float4 {
            if ((unsigned)y >= HH) return make_float4(0.f, 0.f, 0.f, 0.f);
            float4 p = *(const float4*)(pch + y * WW + x0);
            int4   t = *(const int4*)(tch + y * WW + x0);
            float4 v;
            v.x = p.x - (t.x == cls ? 1.0f : 0.0f); v.x *= v.x;
            v.y = p.y - (t.y == cls ? 1.0f : 0.0f); v.y *= v.y;
            v.z = p.z - (t.z == cls ? 1.0f : 0.0f); v.z *= v.z;
            v.w = p.w - (t.w == cls ? 1.0f : 0.0f); v.w *= v.w;
            return v;
        };
        auto load1 = [&](int y, int x) -> float {
            float p = pch[y * WW + x];
            float v = p - (tch[y * WW + x] == cls ? 1.0f : 0.0f);
            return v * v;
        };

        float4 u = load4(y0 - 1);
        float4 c = load4(y0);
#pragma unroll
        for (int i = 0; i < 8; ++i) {
            const int y = y0 + i;
            const float4 d = load4(y + 1);
            float l = __shfl_up_sync(0xffffffffu, c.w, 1);
            float r = __shfl_down_sync(0xffffffffu, c.x, 1);
            if (need_l) l = load1(y, x0 - 1);
            if (need_r) r = load1(y, x0 + 4);
            if (left_edge)  l = 0.0f;
            if (right_edge) r = 0.0f;

            const float S0 = (c.x + u.x) + (d.x + l)   + c.y;
            const float S1 = (c.y + u.y) + (d.y + c.x) + c.z;
            const float S2 = (c.z + u.z) + (d.z + c.y) + c.w;
            const float S3 = (c.w + u.w) + (d.w + c.z) + r;

            const float e0 = fmaxf(fmaf(0.2f, S0, -0.5f), 0.0f);
            const float e1 = fmaxf(fmaf(0.2f, S1, -0.5f), 0.0f);
            const float e2 = fmaxf(fmaf(0.2f, S2, -0.5f), 0.0f);
            const float e3 = fmaxf(fmaf(0.2f, S3, -0.5f), 0.0f);

            __half2 p0 = __floats2half2_rn(e0, e1);
            __half2 p1 = __floats2half2_rn(e2, e3);
            if (WRITE) {
                uint2 s;
                *(__half2*)&s.x = p0;
                *(__half2*)&s.y = p1;
                *(uint2*)(out + y * WW + x0) = s;
            }
            float2 q0 = __half22float2(p0), q1 = __half22float2(p1);
            lmin = fminf(lmin, fminf(fminf(q0.x, q0.y), fminf(q1.x, q1.y)));
            lmax = fmaxf(lmax, fmaxf(fmaxf(q0.x, q0.y), fmaxf(q1.x, q1.y)));
            lsum += (q0.x + q0.y) + (q1.x + q1.y);
            u = c; c = d;
        }
    } else {
        // half2 SIMD path
        const __half2 A2       = __float2half2_rn(A);
        const __half2 zero2    = __float2half2_rn(0.0f);
        const __half2 b01_int  = __floats2half2_rn(BINT + mx0f, BINT);
        const __half2 b23_int  = __floats2half2_rn(BINT, BINT + mx3f);
        const __half2 b01_edge = __floats2half2_rn(BINT + mx0f + DELTA, BINT + DELTA);
        const __half2 b23_edge = __floats2half2_rn(BINT + DELTA, BINT + mx3f + DELTA);
        const __half  hzero    = __ushort_as_half(0);

        auto load2h = [&](int y, __half2& a, __half2& b) {
            if ((unsigned)y >= HH) { a = zero2; b = zero2; return; }
            uint2 v = *(const uint2*)(in + y * WW + x0);
            a = *(__half2*)&v.x; b = *(__half2*)&v.y;
        };

        __half2 u0, u1, c0, c1, d0, d1;
        load2h(y0 - 1, u0, u1);
        load2h(y0, c0, c1);

        __half2 lmin2 = __half2half2(__ushort_as_half(0x7c00));  // +inf
        __half2 lmax2 = zero2;

#pragma unroll
        for (int i = 0; i < 8; ++i) {
            const int y = y0 + i;
            load2h(y + 1, d0, d1);

            __half2 ph1 = __shfl_up_sync(0xffffffffu, c1, 1);    // prev [c2,c3]
            __half2 nh0 = __shfl_down_sync(0xffffffffu, c0, 1);  // next [c0,c1]
            __half l = __high2half(ph1);
            __half r = __low2half(nh0);
            if (need_l) l = in[y * WW + x0 - 1];
            if (left_edge)  l = hzero;
            if (need_r) r = in[y * WW + x0 + 4];
            if (right_edge) r = hzero;

            const __half2 L0 = __halves2half2(l, __low2half(c0));          // [l,  c0]
            const __half2 M  = __halves2half2(__high2half(c0), __low2half(c1)); // [c1, c2]
            const __half2 R1 = __halves2half2(__high2half(c1), r);         // [c3, r]

            const __half2 t0 = __hadd2(__hadd2(u0, c0), d0);
            const __half2 t1 = __hadd2(__hadd2(u1, c1), d1);
            const __half2 S0 = __hadd2(t0, __hadd2(L0, M));
            const __half2 S1 = __hadd2(t1, __hadd2(M, R1));

            const bool ye = (y == 0) || (y == HH - 1);
            const __half2 e01 = __hmax2(__hfma2(A2, S0, ye ? b01_edge : b01_int), zero2);
            const __half2 e23 = __hmax2(__hfma2(A2, S1, ye ? b23_edge : b23_int), zero2);

            if (WRITE) {
                uint2 s;
                *(__half2*)&s.x = e01;
                *(__half2*)&s.y = e23;
                *(uint2*)(out + y * WW + x0) = s;
            }

            lmin2 = __hmin2(lmin2, __hmin2(e01, e23));
            lmax2 = __hmax2(lmax2, __hmax2(e01, e23));
            float2 f0 = __half22float2(e01), f1 = __half22float2(e23);
            lsum += (f0.x + f0.y) + (f1.x + f1.y);

            u0 = c0; u1 = c1; c0 = d0; c1 = d1;
        }
        lmin = fminf(__half2float(__low2half(lmin2)), __half2float(__high2half(lmin2)));
        lmax = fmaxf(__half2float(__low2half(lmax2)), __half2float(__high2half(lmax2)));
    }

    // ---- reduction: warp -> block -> global atomics ----
#pragma unroll
    for (int o = 16; o; o >>= 1) {
        lmin = fminf(lmin, __shfl_xor_sync(0xffffffffu, lmin, o));
        lmax = fmaxf(lmax, __shfl_xor_sync(0xffffffffu, lmax, o));
        lsum += __shfl_xor_sync(0xffffffffu, lsum, o);
    }
    if (lane == 0) {
        rmin[warp] = lmin; rmax[warp] = lmax; rsum[warp] = lsum;
    }
    __syncthreads();
    if (tid == 0) {
        float bm = rmax[0], bn = rmin[0];
        float bs = rsum[0];
#pragma unroll
        for (int i = 1; i < 8; ++i) {
            bm = fmaxf(bm, rmax[i]);
            bn = fminf(bn, rmin[i]);
            bs += rsum[i];
        }
        atomicMax(&g_maxbits[iter][ch], __float_as_uint(bm));
        atomicMin(&g_minbits[iter][ch], __float_as_uint(bn));
        atomicAdd(&g_sum[iter][ch], (double)bs);
    }
}

__global__ void finalize_kernel(float* __restrict__ outp) {
    if (threadIdx.x == 0) {
        double total = 0.0;
        for (int k = 0; k < KIT; ++k) {
            double w = (double)(k + 1) * (double)(k + 1);  // (k+1)^2
            for (int c = 0; c < NCH; ++c) {
                float mnf = __uint_as_float(g_minbits[k][c]);
                float mxf = __uint_as_float(g_maxbits[k][c]);
                double S  = g_sum[k][c];
                float d   = mxf - mnf;
                double ns = (d != 0.0f)
                          ? (S - (double)HW * (double)mnf) / (double)d
                          : S;
                total += w * ns;
            }
        }
        outp[0] = (float)(total / (double)((double)NCH * (double)HW));
    }
}

extern "C" void kernel_launch(void* const* d_in, const int* in_sizes, int n_in,
                              void* d_out, int out_size) {
    const float* pred = (const float*)d_in[0];
    const int* tgt    = (const int*)d_in[1];

    init_stats_kernel<<<1, 512>>>();

    dim3 block(256);
    dim3 grid(1, HH / 16, NCH);  // (1, 32, 32): block covers 512 cols x 16 rows

    // iter 0: bound = (pred - onehot)^2 computed on the fly, writes g_hbuf[0]
    erode_step_kernel<true, true><<<grid, block>>>(pred, tgt, 0, 0);

    // iters 1..8: ping-pong, normalization pushed through the conv
    int src = 0;
    for (int k = 1; k < KIT - 1; ++k) {
        erode_step_kernel<false, true><<<grid, block>>>(pred, tgt, k, src);
        src ^= 1;
    }
    // iter 9: stats only, no field store
    erode_step_kernel<false, false><<<grid, block>>>(pred, tgt, KIT - 1, src);

    finalize_kernel<<<1, 32>>>((float*)d_out);
}

// round 15
// speedup vs baseline: 2.8280x; 1.0684x over previous
#include <cuda_runtime.h>
#include <cuda_fp16.h>

#define HH 512
#define WW 512
#define NCH 32            // B*C = 8*4
#define HW (HH * WW)
#define KIT 10

// Scratch (static device globals — no allocation)
__device__ __half   g_hbuf[2][NCH * HW];   // ping-pong raw erosion fields (2 x 16MB)
__device__ unsigned g_minbits[KIT][NCH];
__device__ unsigned g_maxbits[KIT][NCH];
__device__ double   g_sum[KIT][NCH];

__global__ void init_stats_kernel() {
    int i = threadIdx.x;
    if (i < KIT * NCH) {
        ((unsigned*)g_minbits)[i] = 0x7f800000u;  // +inf
        ((unsigned*)g_maxbits)[i] = 0u;           // erosion >= 0
        ((double*)g_sum)[i] = 0.0;
    }
}

// One erosion iteration. Thread: 8 cols x 8 rows, rolling 3-row half2x4 window.
// Steady-state math in native half2 SIMD. Normalization (e-min)/(max-min) is
// affine-invariant, so fp16 constant precision cancels; only per-element
// rounding noise (same order as the fp16 storage rounding) survives.
//
// Deferred-normalization identity (zero padding of the NORMALIZED field):
//   0.2*sum norm(x_i) - 0.5 = (0.2*inv)*S_raw - (n_present*0.2*inv*mn + 0.5)
template <bool FIRST, bool WRITE>
__global__ void __launch_bounds__(128, 10)
erode_step_kernel(const float* __restrict__ pred,
                  const int* __restrict__ tgt,
                  int iter, int src) {
    __shared__ float rmin[4], rmax[4], rsum[4];

    const int ch     = blockIdx.z;
    const int tid    = threadIdx.x;
    const int lane   = tid & 31;
    const int warp   = tid >> 5;
    const int warp_x = warp & 1;             // 2 warps across x (256 cols each)
    const int warp_y = warp >> 1;            // 2 warps across y (8 rows each)
    const int x0     = warp_x * 256 + lane * 8;
    const int y0     = blockIdx.y * 16 + warp_y * 8;

    float mn = 0.0f, inv = 1.0f;
    if (!FIRST) {
        float a = __uint_as_float(g_minbits[iter - 1][ch]);
        float b = __uint_as_float(g_maxbits[iter - 1][ch]);
        float d = b - a;
        if (d != 0.0f) { mn = a; inv = 1.0f / d; }
    }
    const float A     = 0.2f * inv;
    const float DELTA = 0.2f * inv * mn;           // per-present-tap correction
    const float BINT  = -(5.0f * DELTA + 0.5f);    // all-5-taps bias

    const __half* __restrict__ in = g_hbuf[src] + (size_t)ch * HW;
    __half* __restrict__ out      = g_hbuf[FIRST ? 0 : (src ^ 1)] + (size_t)ch * HW;
    const float* __restrict__ pch = pred + (size_t)ch * HW;
    const int* __restrict__ tch   = tgt + (size_t)(ch >> 2) * HW;
    const int cls = ch & 3;

    const bool left_edge  = (x0 == 0);             // elem 0 has no left tap
    const bool right_edge = (x0 + 7 == WW - 1);    // elem 7 has no right tap
    const float mx0f = left_edge  ? DELTA : 0.0f;
    const float mx7f = right_edge ? DELTA : 0.0f;
    const bool need_l = (lane == 0)  && !left_edge;
    const bool need_r = (lane == 31) && !right_edge;

    float lmin = __uint_as_float(0x7f800000u);
    float lmax = 0.0f;
    float lsum = 0.0f;

    if (FIRST) {
        // fp32 path (mn=0 -> bias = -0.5 everywhere); two 4-col groups per row.
        auto load8 = [&](int y, float4& a, float4& b) {
            if ((unsigned)y >= HH) {
                a = make_float4(0.f, 0.f, 0.f, 0.f);
                b = a; return;
            }
            float4 pa = *(const float4*)(pch + y * WW + x0);
            float4 pb = *(const float4*)(pch + y * WW + x0 + 4);
            int4   ta = *(const int4*)(tch + y * WW + x0);
            int4   tb = *(const int4*)(tch + y * WW + x0 + 4);
            a.x = pa.x - (ta.x == cls ? 1.0f : 0.0f); a.x *= a.x;
            a.y = pa.y - (ta.y == cls ? 1.0f : 0.0f); a.y *= a.y;
            a.z = pa.z - (ta.z == cls ? 1.0f : 0.0f); a.z *= a.z;
            a.w = pa.w - (ta.w == cls ? 1.0f : 0.0f); a.w *= a.w;
            b.x = pb.x - (tb.x == cls ? 1.0f : 0.0f); b.x *= b.x;
            b.y = pb.y - (tb.y == cls ? 1.0f : 0.0f); b.y *= b.y;
            b.z = pb.z - (tb.z == cls ? 1.0f : 0.0f); b.z *= b.z;
            b.w = pb.w - (tb.w == cls ? 1.0f : 0.0f); b.w *= b.w;
        };
        auto load1 = [&](int y, int x) -> float {
            float p = pch[y * WW + x];
            float v = p - (tch[y * WW + x] == cls ? 1.0f : 0.0f);
            return v * v;
        };

        float4 ua, ub, ca, cb, da, db;
        load8(y0 - 1, ua, ub);
        load8(y0, ca, cb);
#pragma unroll
        for (int i = 0; i < 8; ++i) {
            const int y = y0 + i;
            load8(y + 1, da, db);
            float l = __shfl_up_sync(0xffffffffu, cb.w, 1);
            float r = __shfl_down_sync(0xffffffffu, ca.x, 1);
            if (need_l) l = load1(y, x0 - 1);
            if (need_r) r = load1(y, x0 + 8);
            if (left_edge)  l = 0.0f;
            if (right_edge) r = 0.0f;

            const float S0 = (ca.x + ua.x) + (da.x + l)    + ca.y;
            const float S1 = (ca.y + ua.y) + (da.y + ca.x) + ca.z;
            const float S2 = (ca.z + ua.z) + (da.z + ca.y) + ca.w;
            const float S3 = (ca.w + ua.w) + (da.w + ca.z) + cb.x;
            const float S4 = (cb.x + ub.x) + (db.x + ca.w) + cb.y;
            const float S5 = (cb.y + ub.y) + (db.y + cb.x) + cb.z;
            const float S6 = (cb.z + ub.z) + (db.z + cb.y) + cb.w;
            const float S7 = (cb.w + ub.w) + (db.w + cb.z) + r;

            const float e0 = fmaxf(fmaf(0.2f, S0, -0.5f), 0.0f);
            const float e1 = fmaxf(fmaf(0.2f, S1, -0.5f), 0.0f);
            const float e2 = fmaxf(fmaf(0.2f, S2, -0.5f), 0.0f);
            const float e3 = fmaxf(fmaf(0.2f, S3, -0.5f), 0.0f);
            const float e4 = fmaxf(fmaf(0.2f, S4, -0.5f), 0.0f);
            const float e5 = fmaxf(fmaf(0.2f, S5, -0.5f), 0.0f);
            const float e6 = fmaxf(fmaf(0.2f, S6, -0.5f), 0.0f);
            const float e7 = fmaxf(fmaf(0.2f, S7, -0.5f), 0.0f);

            __half2 p0 = __floats2half2_rn(e0, e1);
            __half2 p1 = __floats2half2_rn(e2, e3);
            __half2 p2 = __floats2half2_rn(e4, e5);
            __half2 p3 = __floats2half2_rn(e6, e7);
            if (WRITE) {
                uint4 s;
                *(__half2*)&s.x = p0; *(__half2*)&s.y = p1;
                *(__half2*)&s.z = p2; *(__half2*)&s.w = p3;
                *(uint4*)(out + y * WW + x0) = s;
            }
            float2 q0 = __half22float2(p0), q1 = __half22float2(p1);
            float2 q2 = __half22float2(p2), q3 = __half22float2(p3);
            lmin = fminf(lmin, fminf(fminf(fminf(q0.x, q0.y), fminf(q1.x, q1.y)),
                                     fminf(fminf(q2.x, q2.y), fminf(q3.x, q3.y))));
            lmax = fmaxf(lmax, fmaxf(fmaxf(fmaxf(q0.x, q0.y), fmaxf(q1.x, q1.y)),
                                     fmaxf(fmaxf(q2.x, q2.y), fmaxf(q3.x, q3.y))));
            lsum += ((q0.x + q0.y) + (q1.x + q1.y)) + ((q2.x + q2.y) + (q3.x + q3.y));
            ua = ca; ub = cb; ca = da; cb = db;
        }
    } else {
        // half2x4 SIMD path (8 cols/thread)
        const __half2 A2      = __float2half2_rn(A);
        const __half2 zero2   = __float2half2_rn(0.0f);
        const __half2 D2      = __float2half2_rn(DELTA);
        const __half2 b0_int  = __floats2half2_rn(BINT + mx0f, BINT);
        const __half2 bm_int  = __float2half2_rn(BINT);
        const __half2 b3_int  = __floats2half2_rn(BINT, BINT + mx7f);
        const __half  hzero   = __ushort_as_half(0);

        auto load8h = [&](int y, __half2* v) {
            if ((unsigned)y >= HH) { v[0] = v[1] = v[2] = v[3] = zero2; return; }
            uint4 q = *(const uint4*)(in + y * WW + x0);
            v[0] = *(__half2*)&q.x; v[1] = *(__half2*)&q.y;
            v[2] = *(__half2*)&q.z; v[3] = *(__half2*)&q.w;
        };

        __half2 u[4], c[4], d[4];
        load8h(y0 - 1, u);
        load8h(y0, c);

        __half2 lmin2 = __half2half2(__ushort_as_half(0x7c00));  // +inf
        __half2 lmax2 = zero2;

#pragma unroll
        for (int i = 0; i < 8; ++i) {
            const int y = y0 + i;
            load8h(y + 1, d);

            __half2 ph = __shfl_up_sync(0xffffffffu, c[3], 1);
            __half2 nh = __shfl_down_sync(0xffffffffu, c[0], 1);
            __half l = __high2half(ph);
            __half r = __low2half(nh);
            if (need_l) l = in[y * WW + x0 - 1];
            if (left_edge)  l = hzero;
            if (need_r) r = in[y * WW + x0 + 8];
            if (right_edge) r = hzero;

            // shifted pairs: L_k pairs [x(2k-1), x(2k)]
            const __half2 L0 = __halves2half2(l, __low2half(c[0]));
            const __half2 L1 = __halves2half2(__high2half(c[0]), __low2half(c[1]));
            const __half2 L2 = __halves2half2(__high2half(c[1]), __low2half(c[2]));
            const __half2 L3 = __halves2half2(__high2half(c[2]), __low2half(c[3]));
            const __half2 R3 = __halves2half2(__high2half(c[3]), r);

            const __half2 S0 = __hadd2(__hadd2(__hadd2(u[0], c[0]), __hadd2(d[0], L0)), L1);
            const __half2 S1 = __hadd2(__hadd2(__hadd2(u[1], c[1]), __hadd2(d[1], L1)), L2);
            const __half2 S2 = __hadd2(__hadd2(__hadd2(u[2], c[2]), __hadd2(d[2], L2)), L3);
            const __half2 S3 = __hadd2(__hadd2(__hadd2(u[3], c[3]), __hadd2(d[3], L3)), R3);

            const bool ye = (y == 0) || (y == HH - 1);
            __half2 b0 = b0_int, bm = bm_int, b3 = b3_int;
            if (ye) { b0 = __hadd2(b0, D2); bm = __hadd2(bm, D2); b3 = __hadd2(b3, D2); }

            const __half2 e0 = __hmax2(__hfma2(A2, S0, b0), zero2);
            const __half2 e1 = __hmax2(__hfma2(A2, S1, bm), zero2);
            const __half2 e2 = __hmax2(__hfma2(A2, S2, bm), zero2);
            const __half2 e3 = __hmax2(__hfma2(A2, S3, b3), zero2);

            if (WRITE) {
                uint4 s;
                *(__half2*)&s.x = e0; *(__half2*)&s.y = e1;
                *(__half2*)&s.z = e2; *(__half2*)&s.w = e3;
                *(uint4*)(out + y * WW + x0) = s;
            }

            lmin2 = __hmin2(lmin2, __hmin2(__hmin2(e0, e1), __hmin2(e2, e3)));
            lmax2 = __hmax2(lmax2, __hmax2(__hmax2(e0, e1), __hmax2(e2, e3)));
            // row sum in half2 (values <= ~1, 8 per row: exact enough; noise
            // averages out across 32768 rows/channel)
            __half2 srow = __hadd2(__hadd2(e0, e1), __hadd2(e2, e3));
            float2 fs = __half22float2(srow);
            lsum += fs.x + fs.y;

            u[0] = c[0]; u[1] = c[1]; u[2] = c[2]; u[3] = c[3];
            c[0] = d[0]; c[1] = d[1]; c[2] = d[2]; c[3] = d[3];
        }
        lmin = fminf(__half2float(__low2half(lmin2)), __half2float(__high2half(lmin2)));
        lmax = fmaxf(__half2float(__low2half(lmax2)), __half2float(__high2half(lmax2)));
    }

    // ---- reduction: warp -> block -> global atomics ----
#pragma unroll
    for (int o = 16; o; o >>= 1) {
        lmin = fminf(lmin, __shfl_xor_sync(0xffffffffu, lmin, o));
        lmax = fmaxf(lmax, __shfl_xor_sync(0xffffffffu, lmax, o));
        lsum += __shfl_xor_sync(0xffffffffu, lsum, o);
    }
    if (lane == 0) {
        rmin[warp] = lmin; rmax[warp] = lmax; rsum[warp] = lsum;
    }
    __syncthreads();
    if (tid == 0) {
        float bm = rmax[0], bn = rmin[0];
        float bs = rsum[0];
#pragma unroll
        for (int i = 1; i < 4; ++i) {
            bm = fmaxf(bm, rmax[i]);
            bn = fminf(bn, rmin[i]);
            bs += rsum[i];
        }
        atomicMax(&g_maxbits[iter][ch], __float_as_uint(bm));
        atomicMin(&g_minbits[iter][ch], __float_as_uint(bn));
        atomicAdd(&g_sum[iter][ch], (double)bs);
    }
}

__global__ void finalize_kernel(float* __restrict__ outp) {
    if (threadIdx.x == 0) {
        double total = 0.0;
        for (int k = 0; k < KIT; ++k) {
            double w = (double)(k + 1) * (double)(k + 1);  // (k+1)^2
            for (int c = 0; c < NCH; ++c) {
                float mnf = __uint_as_float(g_minbits[k][c]);
                float mxf = __uint_as_float(g_maxbits[k][c]);
                double S  = g_sum[k][c];
                float d   = mxf - mnf;
                double ns = (d != 0.0f)
                          ? (S - (double)HW * (double)mnf) / (double)d
                          : S;
                total += w * ns;
            }
        }
        outp[0] = (float)(total / (double)((double)NCH * (double)HW));
    }
}

extern "C" void kernel_launch(void* const* d_in, const int* in_sizes, int n_in,
                              void* d_out, int out_size) {
    const float* pred = (const float*)d_in[0];
    const int* tgt    = (const int*)d_in[1];

    init_stats_kernel<<<1, 512>>>();

    dim3 block(128);
    dim3 grid(1, HH / 16, NCH);  // (1, 32, 32): block covers 512 cols x 16 rows

    // iter 0: bound = (pred - onehot)^2 computed on the fly, writes g_hbuf[0]
    erode_step_kernel<true, true><<<grid, block>>>(pred, tgt, 0, 0);

    // iters 1..8: ping-pong, normalization pushed through the conv
    int src = 0;
    for (int k = 1; k < KIT - 1; ++k) {
        erode_step_kernel<false, true><<<grid, block>>>(pred, tgt, k, src);
        src ^= 1;
    }
    // iter 9: stats only, no field store
    erode_step_kernel<false, false><<<grid, block>>>(pred, tgt, KIT - 1, src);

    finalize_kernel<<<1, 32>>>((float*)d_out);
}